// round 1
// baseline (speedup 1.0000x reference)
#include <cuda_runtime.h>

// Lorenz96 RK4 step, one thread per row of N=40 states.
// dxdt[i] = (x[i+1] - x[i-2]) * x[i-1] - x[i] + FORCE   (indices mod N)
// out = x + dt/6 * (k1 + 2 k2 + 2 k3 + k4)

#define N_STATE 40
#define FORCE_C 8.0f

__device__ __forceinline__ void lorenz_dxdt(const float* __restrict__ x,
                                            float* __restrict__ k) {
#pragma unroll
    for (int i = 0; i < N_STATE; i++) {
        const int ip1 = (i + 1) % N_STATE;
        const int im2 = (i + N_STATE - 2) % N_STATE;
        const int im1 = (i + N_STATE - 1) % N_STATE;
        k[i] = fmaf(x[ip1] - x[im2], x[im1], FORCE_C - x[i]);
    }
}

__global__ __launch_bounds__(256)
void lorenz96_rk4_kernel(const float* __restrict__ x0,
                         const float* __restrict__ dt_ptr,
                         float* __restrict__ out,
                         int batch) {
    const int row = blockIdx.x * blockDim.x + threadIdx.x;
    if (row >= batch) return;

    const float dt = __ldg(dt_ptr);
    const float half_dt = 0.5f * dt;
    const float sixth_dt = dt * (1.0f / 6.0f);

    float x[N_STATE], y[N_STATE], k[N_STATE], acc[N_STATE];

    // Vectorized load: 10 x float4 (row stride 160 B, 16B-aligned)
    const float4* src = reinterpret_cast<const float4*>(x0) + (size_t)row * (N_STATE / 4);
#pragma unroll
    for (int j = 0; j < N_STATE / 4; j++) {
        float4 v = src[j];
        x[4 * j + 0] = v.x;
        x[4 * j + 1] = v.y;
        x[4 * j + 2] = v.z;
        x[4 * j + 3] = v.w;
    }

    // k1
    lorenz_dxdt(x, k);
#pragma unroll
    for (int i = 0; i < N_STATE; i++) {
        acc[i] = k[i];
        y[i] = fmaf(half_dt, k[i], x[i]);
    }

    // k2
    lorenz_dxdt(y, k);
#pragma unroll
    for (int i = 0; i < N_STATE; i++) {
        acc[i] = fmaf(2.0f, k[i], acc[i]);
        y[i] = fmaf(half_dt, k[i], x[i]);
    }

    // k3
    lorenz_dxdt(y, k);
#pragma unroll
    for (int i = 0; i < N_STATE; i++) {
        acc[i] = fmaf(2.0f, k[i], acc[i]);
        y[i] = fmaf(dt, k[i], x[i]);
    }

    // k4
    lorenz_dxdt(y, k);

    // out = x + dt/6 * (acc + k4)
    float4* dst = reinterpret_cast<float4*>(out) + (size_t)row * (N_STATE / 4);
#pragma unroll
    for (int j = 0; j < N_STATE / 4; j++) {
        float4 v;
        v.x = fmaf(sixth_dt, acc[4 * j + 0] + k[4 * j + 0], x[4 * j + 0]);
        v.y = fmaf(sixth_dt, acc[4 * j + 1] + k[4 * j + 1], x[4 * j + 1]);
        v.z = fmaf(sixth_dt, acc[4 * j + 2] + k[4 * j + 2], x[4 * j + 2]);
        v.w = fmaf(sixth_dt, acc[4 * j + 3] + k[4 * j + 3], x[4 * j + 3]);
        dst[j] = v;
    }
}

extern "C" void kernel_launch(void* const* d_in, const int* in_sizes, int n_in,
                              void* d_out, int out_size) {
    const float* x0 = (const float*)d_in[0];
    // d_in[1] is t (unused, autonomous system)
    const float* dt = (const float*)d_in[2];
    float* out = (float*)d_out;

    const int batch = in_sizes[0] / N_STATE;
    const int threads = 256;
    const int blocks = (batch + threads - 1) / threads;
    lorenz96_rk4_kernel<<<blocks, threads>>>(x0, dt, out, batch);
}